// round 9
// baseline (speedup 1.0000x reference)
#include <cuda_runtime.h>
#include <cuda_bf16.h>

// Cost volume: out[b,h,w,(9i+jj)%81] = (1/H) * sum_c x1[b,h,w,c] * x2[b,h-i,w-jj,c]
// B=8, H=W=C=128, sr=4, D=9, OC=81. Zero padding outside.
//
// Block = (b, band of 2 output rows). 512 threads = 128 w-lanes x 4 c-groups (32 ch each).
// A (x1 band slice) lives in REGISTERS (2 rows x 32 c per thread), loaded once.
// Fully pipelined rounds, ONE barrier each: stage B(rr+1) into Bs[(rr+1)&1]  ||
// flush round rr-1 from Ps[(rr-1)&1]  ||  compute rr from Bs[rr&1] into Ps[rr&1].
// Slot s reads Bs[w+s] = x2[r][w+s-4] => jj = 4 - s.

typedef unsigned long long u64;

#define Bb    8
#define Hh    128
#define Ww    128
#define Cc    128
#define OC    81
#define NT    512
#define BPAD  132        // Bs row stride: 528B (16B-aligned); 132 mod 32 = 4 -> conflict-free
#define APAD  68         // A-staging stride: 272B (16B-aligned); 68 mod 32 = 4 -> conflict-free
#define WB    136        // x2 row width incl. +/-4 halo

#define BS_FLOATS (WB * BPAD)          // 17952 per buffer (>= A-stage: 2*128*68 = 17408)
#define PS_FLOATS (4 * 2 * Ww * 9)     // 9216 per buffer
#define SMEM_BYTES ((2 * BS_FLOATS + 2 * PS_FLOATS) * 4)   // 217344 B <= 232448

__device__ __forceinline__ u64 fmax2(u64 a, u64 b, u64 c) {
    u64 d;
    asm("fma.rn.f32x2 %0, %1, %2, %3;" : "=l"(d) : "l"(a), "l"(b), "l"(c));
    return d;
}
__device__ __forceinline__ float hsum_x2(u64 p) {
    float lo, hi;
    asm("mov.b64 {%0, %1}, %2;" : "=f"(lo), "=f"(hi) : "l"(p));
    return lo + hi;
}
__device__ __forceinline__ void f4_to_u64(const float4& v, u64& p0, u64& p1) {
    asm("mov.b64 %0, {%1, %2};" : "=l"(p0) : "f"(v.x), "f"(v.y));
    asm("mov.b64 %0, {%1, %2};" : "=l"(p1) : "f"(v.z), "f"(v.w));
}

__device__ __forceinline__ void stage_b(const float* __restrict__ x2b,
                                        float* __restrict__ Bs, int r, int tid) {
    // x2 row r, full C, +/-4 halo zero-filled. 4352 float4, coalesced LDG.
    for (int idx = tid; idx < WB * (Cc / 4); idx += NT) {
        int wp = idx >> 5;
        int c4 = idx & 31;
        int w2 = wp - 4;
        float4 v = make_float4(0.f, 0.f, 0.f, 0.f);
        if ((unsigned)w2 < (unsigned)Ww)
            v = *reinterpret_cast<const float4*>(x2b + (((r << 7) + w2) << 7) + (c4 << 2));
        *reinterpret_cast<float4*>(Bs + wp * BPAD + (c4 << 2)) = v;
    }
}

// Sum 4 c-group partials, scale, write final outputs for round rr.
__device__ __forceinline__ void flush_ps(const float* __restrict__ Ps,
                                         float* __restrict__ outb,
                                         int rr, int tid, float invH) {
    const int lo = (rr == 9) ? 1 : 0;
    const int hi = (rr == 0) ? 0 : 1;
    const int total = (hi - lo + 1) * Ww * 9;
    for (int idx = tid; idx < total; idx += NT) {
        int rowl = idx / (Ww * 9);
        int rem  = idx - rowl * (Ww * 9);
        int ww   = rem / 9;
        int s    = rem - ww * 9;
        int rw   = lo + rowl;
        int off  = (rw * Ww + ww) * 9 + s;
        float v = Ps[off] + Ps[2304 + off] + Ps[2 * 2304 + off] + Ps[3 * 2304 + off];
        int oc = 9 * (rw + 4 - rr) + (4 - s);   // i = h - r, jj = 4 - s
        if (oc < 0) oc += OC;
        outb[(size_t)(rw * Ww + ww) * OC + oc] = v * invH;
    }
}

__global__ void __launch_bounds__(NT, 1)
cost_volume_kernel(const float* __restrict__ x1,
                   const float* __restrict__ x2,
                   float* __restrict__ out) {
    extern __shared__ float sm[];
    float* Bs0 = sm;                       // [136][132] ping (round parity 0)
    float* Bs1 = sm + BS_FLOATS;           // [136][132] pong; also A-staging slab at init
    float* Ps0 = sm + 2 * BS_FLOATS;       // [4][2][128][9] partials, parity 0
    float* Ps1 = Ps0 + PS_FLOATS;          // parity 1

    const int tid  = threadIdx.x;
    const int w    = tid & 127;
    const int cg   = tid >> 7;             // c-group 0..3, owns c in [32*cg, 32*cg+32)
    const int bblk = blockIdx.x >> 6;
    const int h0   = (blockIdx.x & 63) << 1;
    const float invH = 1.0f / 128.0f;

    const float* x1b  = x1 + ((size_t)(bblk * Hh + h0)) * (Ww * Cc);
    const float* x2b  = x2 + ((size_t)bblk) * (Hh * Ww * Cc);
    float*       outb = out + ((size_t)(bblk * Hh + h0)) * (Ww * OC);

    // Edge bands: some (rw, i) channels have no valid x2 row -> pre-zero the band.
    if (h0 < 4 || h0 > 122) {
        for (int idx = tid; idx < 2 * Ww * OC; idx += NT) outb[idx] = 0.0f;
    }

    // Prologue B stage for round 0 (Bs0); overlaps with A staging below (disjoint slabs).
    {
        int r0 = h0 - 4;
        if ((unsigned)r0 < (unsigned)Hh) stage_b(x2b, Bs0, r0, tid);
    }

    // ---- Load A into registers: a[rw][16] u64 = 2 rows x 32 c, via 2 staged c-halves ----
    u64 a[2][16];
#pragma unroll
    for (int hc = 0; hc < 2; hc++) {
        // Stage x1 band c-half into Bs1 slab: 2*128*16 float4, coalesced.
        for (int idx = tid; idx < 2 * Ww * 16; idx += NT) {
            int row = idx >> 11;
            int rem = idx & 2047;
            int ww  = rem >> 4;
            int c4  = rem & 15;
            float4 v = *reinterpret_cast<const float4*>(
                x1b + (((row << 7) + ww) << 7) + (hc << 6) + (c4 << 2));
            *reinterpret_cast<float4*>(Bs1 + (row * Ww + ww) * APAD + (c4 << 2)) = v;
        }
        __syncthreads();
        if ((cg >> 1) == hc) {
            const int cl = (cg & 1) << 5;   // c offset within half (0 or 32)
#pragma unroll
            for (int rw = 0; rw < 2; rw++) {
#pragma unroll
                for (int k = 0; k < 8; k++) {
                    float4 v = *reinterpret_cast<const float4*>(
                        Bs1 + (rw * Ww + w) * APAD + cl + (k << 2));
                    f4_to_u64(v, a[rw][2 * k], a[rw][2 * k + 1]);
                }
            }
        }
        __syncthreads();
    }

    // ---- Pipelined main loop: one barrier per round ----
    int pend = -1;
    for (int rr = 0; rr < 10; rr++) {
        const float* Bcur = (rr & 1) ? Bs1 : Bs0;
        float*       Bnxt = (rr & 1) ? Bs0 : Bs1;
        float*       Pcur = (rr & 1) ? Ps1 : Ps0;

        // Stage next round's B row (disjoint buffer; LDGs issue early, latency hidden)
        if (rr < 9) {
            int rn = h0 - 4 + rr + 1;
            if ((unsigned)rn < (unsigned)Hh) stage_b(x2b, Bnxt, rn, tid);
        }
        // Flush previous round's partials (disjoint Ps buffer)
        if (pend >= 0) flush_ps((pend & 1) ? Ps1 : Ps0, outb, pend, tid, invH);

        const int r = h0 - 4 + rr;
        int np = -1;
        if ((unsigned)r < (unsigned)Hh) {
            const float* Bbase = Bcur + w * BPAD + (cg << 5);
            u64 acc[2][9];
#pragma unroll
            for (int rw = 0; rw < 2; rw++)
#pragma unroll
                for (int s = 0; s < 9; s++) acc[rw][s] = 0ull;

#pragma unroll
            for (int k = 0; k < 8; k++) {
#pragma unroll
                for (int s = 0; s < 9; s++) {
                    float4 v = *reinterpret_cast<const float4*>(Bbase + s * BPAD + (k << 2));
                    u64 b0, b1;
                    f4_to_u64(v, b0, b1);
                    acc[0][s] = fmax2(a[0][2 * k],     b0, acc[0][s]);
                    acc[0][s] = fmax2(a[0][2 * k + 1], b1, acc[0][s]);
                    acc[1][s] = fmax2(a[1][2 * k],     b0, acc[1][s]);
                    acc[1][s] = fmax2(a[1][2 * k + 1], b1, acc[1][s]);
                }
            }
            // Partials: Ps[cg][(rw*128+w)*9+s]; lane stride 9 (coprime 32) conflict-free
            float* Pmy = Pcur + cg * 2304;
#pragma unroll
            for (int rw = 0; rw < 2; rw++)
#pragma unroll
                for (int s = 0; s < 9; s++)
                    Pmy[(rw * Ww + w) * 9 + s] = hsum_x2(acc[rw][s]);
            np = rr;
        }
        __syncthreads();
        pend = np;
    }
    if (pend >= 0) flush_ps((pend & 1) ? Ps1 : Ps0, outb, pend, tid, invH);
}

extern "C" void kernel_launch(void* const* d_in, const int* in_sizes, int n_in,
                              void* d_out, int out_size) {
    const float* x1 = (const float*)d_in[0];
    const float* x2 = (const float*)d_in[1];
    float* out = (float*)d_out;

    static bool attr_set = false;
    if (!attr_set) {
        cudaFuncSetAttribute(cost_volume_kernel,
                             cudaFuncAttributeMaxDynamicSharedMemorySize, SMEM_BYTES);
        attr_set = true;
    }

    dim3 grid(Bb * (Hh / 2));  // 512 blocks
    cost_volume_kernel<<<grid, NT, SMEM_BYTES>>>(x1, x2, out);
}

// round 10
// speedup vs baseline: 1.0362x; 1.0362x over previous
#include <cuda_runtime.h>
#include <cuda_bf16.h>

// Cost volume: out[b,h,w,(9i+jj)%81] = (1/H) * sum_c x1[b,h,w,c] * x2[b,h-i,w-jj,c]
// B=8, H=W=C=128, sr=4, D=9, OC=81. Zero padding outside.
//
// Block = (b, band of 2 output rows). 512 threads = 128 w-lanes x 4 c-groups (32 ch each).
// A (x1 band slice) in REGISTERS (2 rows x 32 c per thread), loaded once.
// Per round: stage B row full-C into SMEM; compute runs TWO SLOT PASSES (s=0..4, s=5..8)
// over the k-loop — lower acc live-range frees registers for deeper LDS pipelining.
// Partials in Ps[4] slab; flush overlaps next round's staging. Write-once coalesced GMEM.
// Slot s reads Bs[w+s] = x2[r][w+s-4] => jj = 4 - s.

typedef unsigned long long u64;

#define Bb    8
#define Hh    128
#define Ww    128
#define Cc    128
#define OC    81
#define NT    512
#define BPAD  132        // Bs row stride: 528B (16B-aligned); 132 mod 32 = 4 -> conflict-free
#define APAD  68         // A-staging stride: 272B (16B-aligned); 68 mod 32 = 4 -> conflict-free
#define WB    136        // x2 row width incl. +/-4 halo

#define BS_FLOATS (WB * BPAD)          // 17952 (>= A-stage: 2*128*68 = 17408)
#define PS_FLOATS (4 * 2 * Ww * 9)     // 9216
#define SMEM_BYTES ((BS_FLOATS + PS_FLOATS) * 4)   // 108672 B

__device__ __forceinline__ u64 fmax2(u64 a, u64 b, u64 c) {
    u64 d;
    asm("fma.rn.f32x2 %0, %1, %2, %3;" : "=l"(d) : "l"(a), "l"(b), "l"(c));
    return d;
}
__device__ __forceinline__ float hsum_x2(u64 p) {
    float lo, hi;
    asm("mov.b64 {%0, %1}, %2;" : "=f"(lo), "=f"(hi) : "l"(p));
    return lo + hi;
}
__device__ __forceinline__ void f4_to_u64(const float4& v, u64& p0, u64& p1) {
    asm("mov.b64 %0, {%1, %2};" : "=l"(p0) : "f"(v.x), "f"(v.y));
    asm("mov.b64 %0, {%1, %2};" : "=l"(p1) : "f"(v.z), "f"(v.w));
}

__device__ __forceinline__ void stage_b(const float* __restrict__ x2b,
                                        float* __restrict__ Bs, int r, int tid) {
    // x2 row r, full C, +/-4 halo zero-filled. 4352 float4, coalesced LDG.
    for (int idx = tid; idx < WB * (Cc / 4); idx += NT) {
        int wp = idx >> 5;
        int c4 = idx & 31;
        int w2 = wp - 4;
        float4 v = make_float4(0.f, 0.f, 0.f, 0.f);
        if ((unsigned)w2 < (unsigned)Ww)
            v = *reinterpret_cast<const float4*>(x2b + (((r << 7) + w2) << 7) + (c4 << 2));
        *reinterpret_cast<float4*>(Bs + wp * BPAD + (c4 << 2)) = v;
    }
}

// Sum 4 c-group partials, scale, write final outputs for round rr.
__device__ __forceinline__ void flush_ps(const float* __restrict__ Ps,
                                         float* __restrict__ outb,
                                         int rr, int tid, float invH) {
    const int lo = (rr == 9) ? 1 : 0;
    const int hi = (rr == 0) ? 0 : 1;
    const int total = (hi - lo + 1) * Ww * 9;
    for (int idx = tid; idx < total; idx += NT) {
        int rowl = idx / (Ww * 9);
        int rem  = idx - rowl * (Ww * 9);
        int ww   = rem / 9;
        int s    = rem - ww * 9;
        int rw   = lo + rowl;
        int off  = (rw * Ww + ww) * 9 + s;
        float v = Ps[off] + Ps[2304 + off] + Ps[2 * 2304 + off] + Ps[3 * 2304 + off];
        int oc = 9 * (rw + 4 - rr) + (4 - s);   // i = h - r, jj = 4 - s
        if (oc < 0) oc += OC;
        outb[(size_t)(rw * Ww + ww) * OC + oc] = v * invH;
    }
}

// One slot pass: NJ slots starting at SOFF, full k loop, low acc live-range.
template<int NJ, int SOFF>
__device__ __forceinline__ void compute_pass(const u64 a[2][16],
                                             const float* __restrict__ Bbase,
                                             float* __restrict__ Pmy, int w) {
    u64 acc[2][NJ];
#pragma unroll
    for (int rw = 0; rw < 2; rw++)
#pragma unroll
        for (int t = 0; t < NJ; t++) acc[rw][t] = 0ull;

#pragma unroll
    for (int k = 0; k < 8; k++) {
#pragma unroll
        for (int t = 0; t < NJ; t++) {
            float4 v = *reinterpret_cast<const float4*>(Bbase + (SOFF + t) * BPAD + (k << 2));
            u64 b0, b1;
            f4_to_u64(v, b0, b1);
            acc[0][t] = fmax2(a[0][2 * k],     b0, acc[0][t]);
            acc[0][t] = fmax2(a[0][2 * k + 1], b1, acc[0][t]);
            acc[1][t] = fmax2(a[1][2 * k],     b0, acc[1][t]);
            acc[1][t] = fmax2(a[1][2 * k + 1], b1, acc[1][t]);
        }
    }
    // Ps[(rw*128+w)*9 + s]; lane stride 9 (coprime 32) -> conflict-free scalar STS
#pragma unroll
    for (int rw = 0; rw < 2; rw++)
#pragma unroll
        for (int t = 0; t < NJ; t++)
            Pmy[(rw * Ww + w) * 9 + SOFF + t] = hsum_x2(acc[rw][t]);
}

__global__ void __launch_bounds__(NT, 1)
cost_volume_kernel(const float* __restrict__ x1,
                   const float* __restrict__ x2,
                   float* __restrict__ out) {
    extern __shared__ float sm[];
    float* Bs = sm;                 // [136][132]; also reused as A staging buffer at init
    float* Ps = sm + BS_FLOATS;     // [4][2][128][9] partials per c-group

    const int tid  = threadIdx.x;
    const int w    = tid & 127;
    const int cg   = tid >> 7;               // c-group 0..3, owns c in [32*cg, 32*cg+32)
    const int bblk = blockIdx.x >> 6;
    const int h0   = (blockIdx.x & 63) << 1;
    const float invH = 1.0f / 128.0f;

    const float* x1b  = x1 + ((size_t)(bblk * Hh + h0)) * (Ww * Cc);
    const float* x2b  = x2 + ((size_t)bblk) * (Hh * Ww * Cc);
    float*       outb = out + ((size_t)(bblk * Hh + h0)) * (Ww * OC);

    // Edge bands: some (rw, i) channels have no valid x2 row -> pre-zero the band.
    if (h0 < 4 || h0 > 122) {
        for (int idx = tid; idx < 2 * Ww * OC; idx += NT) outb[idx] = 0.0f;
    }

    // ---- Load A into registers: a[rw][16] u64 = 2 rows x 32 c, via 2 staged c-halves ----
    u64 a[2][16];
#pragma unroll
    for (int hc = 0; hc < 2; hc++) {
        for (int idx = tid; idx < 2 * Ww * 16; idx += NT) {
            int row = idx >> 11;
            int rem = idx & 2047;
            int ww  = rem >> 4;
            int c4  = rem & 15;
            float4 v = *reinterpret_cast<const float4*>(
                x1b + (((row << 7) + ww) << 7) + (hc << 6) + (c4 << 2));
            *reinterpret_cast<float4*>(Bs + (row * Ww + ww) * APAD + (c4 << 2)) = v;
        }
        __syncthreads();
        if ((cg >> 1) == hc) {
            const int cl = (cg & 1) << 5;   // c offset within half (0 or 32)
#pragma unroll
            for (int rw = 0; rw < 2; rw++) {
#pragma unroll
                for (int k = 0; k < 8; k++) {
                    float4 v = *reinterpret_cast<const float4*>(
                        Bs + (rw * Ww + w) * APAD + cl + (k << 2));
                    f4_to_u64(v, a[rw][2 * k], a[rw][2 * k + 1]);
                }
            }
        }
        __syncthreads();
    }

    // ---- Main loop over 10 x2 rows ----
    const float* Bbase = Bs + w * BPAD + (cg << 5);
    float* Pmy = Ps + cg * 2304;
    int pend = -1;
    for (int rr = 0; rr < 10; rr++) {
        const int r = h0 - 4 + rr;
        const bool rvalid = ((unsigned)r < (unsigned)Hh);

        __syncthreads();  // compute(rr-1) done reading Bs / writing Ps

        if (rvalid) stage_b(x2b, Bs, r, tid);            // GMEM latency overlapped by flush
        if (pend >= 0) flush_ps(Ps, outb, pend, tid, invH);

        __syncthreads();  // Bs staged; Ps consumed

        if (rvalid) {
            compute_pass<5, 0>(a, Bbase, Pmy, w);
            compute_pass<4, 5>(a, Bbase, Pmy, w);
            pend = rr;
        } else {
            pend = -1;
        }
    }
    __syncthreads();
    if (pend >= 0) flush_ps(Ps, outb, pend, tid, invH);
}

extern "C" void kernel_launch(void* const* d_in, const int* in_sizes, int n_in,
                              void* d_out, int out_size) {
    const float* x1 = (const float*)d_in[0];
    const float* x2 = (const float*)d_in[1];
    float* out = (float*)d_out;

    static bool attr_set = false;
    if (!attr_set) {
        cudaFuncSetAttribute(cost_volume_kernel,
                             cudaFuncAttributeMaxDynamicSharedMemorySize, SMEM_BYTES);
        attr_set = true;
    }

    dim3 grid(Bb * (Hh / 2));  // 512 blocks
    cost_volume_kernel<<<grid, NT, SMEM_BYTES>>>(x1, x2, out);
}

// round 11
// speedup vs baseline: 1.0821x; 1.0443x over previous
#include <cuda_runtime.h>
#include <cuda_bf16.h>

// Cost volume: out[b,h,w,(9i+jj)%81] = (1/H) * sum_c x1[b,h,w,c] * x2[b,h-i,w-jj,c]
// B=8, H=W=C=128, sr=4, D=9, OC=81. Zero padding outside.
//
// Block = (b, band of 2 output rows). 512 threads = 64 w-PAIRS x 8 c-groups (16 ch each).
// Each thread owns TWO adjacent w positions: slots share B rows, so a 3-slot pass needs
// only 4 B-row loads for 12 dot-chains (6 FMA-pairs per LDS.128, was 4). B rows stored
// with per-row XOR swizzle (c ^ ((row>>1)&7)) -> conflict-free at lane row-stride 2.
// A in registers (2h x 2w x 16c). Partials in Ps[8] slab; flush overlaps staging.
// Slot s reads Bs[w+s] = x2[r][w+s-4] => jj = 4 - s.

typedef unsigned long long u64;

#define Bb    8
#define Hh    128
#define Ww    128
#define Cc    128
#define OC    81
#define NT    512
#define BPAD  132        // Bs row stride: 528B (16B-aligned)
#define APAD  68         // A-staging stride: 272B (16B-aligned)
#define WB    136        // x2 row width incl. +/-4 halo

#define BS_FLOATS (WB * BPAD)            // 17952 (>= A-stage: 2*128*68 = 17408)
#define PS_FLOATS (8 * 2 * Ww * 9)       // 18432
#define SMEM_BYTES ((BS_FLOATS + PS_FLOATS) * 4)   // 145536 B

__device__ __forceinline__ u64 fmax2(u64 a, u64 b, u64 c) {
    u64 d;
    asm("fma.rn.f32x2 %0, %1, %2, %3;" : "=l"(d) : "l"(a), "l"(b), "l"(c));
    return d;
}
__device__ __forceinline__ float hsum_x2(u64 p) {
    float lo, hi;
    asm("mov.b64 {%0, %1}, %2;" : "=f"(lo), "=f"(hi) : "l"(p));
    return lo + hi;
}
__device__ __forceinline__ void f4_to_u64(const float4& v, u64& p0, u64& p1) {
    asm("mov.b64 %0, {%1, %2};" : "=l"(p0) : "f"(v.x), "f"(v.y));
    asm("mov.b64 %0, {%1, %2};" : "=l"(p1) : "f"(v.z), "f"(v.w));
}

__device__ __forceinline__ void stage_b(const float* __restrict__ x2b,
                                        float* __restrict__ Bs, int r, int tid) {
    // x2 row r, full C, +/-4 halo zero-filled, XOR-swizzled columns. Coalesced LDG.
    for (int idx = tid; idx < WB * 32; idx += NT) {
        int wp = idx >> 5;
        int c4 = idx & 31;
        int w2 = wp - 4;
        float4 v = make_float4(0.f, 0.f, 0.f, 0.f);
        if ((unsigned)w2 < (unsigned)Ww)
            v = *reinterpret_cast<const float4*>(x2b + (((r << 7) + w2) << 7) + (c4 << 2));
        int ce = c4 ^ ((wp >> 1) & 7);
        *reinterpret_cast<float4*>(Bs + wp * BPAD + (ce << 2)) = v;
    }
}

// Sum 8 c-group partials, scale, write final outputs for round rr.
__device__ __forceinline__ void flush_ps(const float* __restrict__ Ps,
                                         float* __restrict__ outb,
                                         int rr, int tid, float invH) {
    const int lo = (rr == 9) ? 1 : 0;
    const int hi = (rr == 0) ? 0 : 1;
    const int total = (hi - lo + 1) * Ww * 9;
    for (int idx = tid; idx < total; idx += NT) {
        int rowl = idx / (Ww * 9);
        int rem  = idx - rowl * (Ww * 9);
        int ww   = rem / 9;
        int s    = rem - ww * 9;
        int rw   = lo + rowl;
        int off  = (rw * Ww + ww) * 9 + s;
        float v = 0.0f;
#pragma unroll
        for (int g = 0; g < 8; g++) v += Ps[g * 2304 + off];
        int oc = 9 * (rw + 4 - rr) + (4 - s);   // i = h - r, jj = 4 - s
        if (oc < 0) oc += OC;
        outb[(size_t)(rw * Ww + ww) * OC + oc] = v * invH;
    }
}

// One slot pass: slots SOFF..SOFF+2 for both w-positions; 4 B-row loads per k-step.
template<int SOFF>
__device__ __forceinline__ void compute_pass(const u64 a[2][2][8],
                                             const float* __restrict__ Bs,
                                             float* __restrict__ Pmy,
                                             int wp, int w0, int cbase) {
    u64 acc[2][2][3];
#pragma unroll
    for (int hr = 0; hr < 2; hr++)
#pragma unroll
        for (int wq = 0; wq < 2; wq++)
#pragma unroll
            for (int t = 0; t < 3; t++) acc[hr][wq][t] = 0ull;

#pragma unroll
    for (int k = 0; k < 4; k++) {
        u64 b[4][2];
#pragma unroll
        for (int t = 0; t < 4; t++) {
            int R = w0 + SOFF + t;                        // B row (2wp + SOFF + t)
            int x = (wp + ((SOFF + t) >> 1)) & 7;         // (R>>1)&7
            float4 v = *reinterpret_cast<const float4*>(
                Bs + R * BPAD + (((cbase + k) ^ x) << 2));
            f4_to_u64(v, b[t][0], b[t][1]);
        }
#pragma unroll
        for (int hr = 0; hr < 2; hr++)
#pragma unroll
            for (int wq = 0; wq < 2; wq++)
#pragma unroll
                for (int t = 0; t < 3; t++) {
                    acc[hr][wq][t] = fmax2(a[hr][wq][2 * k],     b[wq + t][0], acc[hr][wq][t]);
                    acc[hr][wq][t] = fmax2(a[hr][wq][2 * k + 1], b[wq + t][1], acc[hr][wq][t]);
                }
    }
#pragma unroll
    for (int hr = 0; hr < 2; hr++)
#pragma unroll
        for (int wq = 0; wq < 2; wq++)
#pragma unroll
            for (int t = 0; t < 3; t++)
                Pmy[(hr * Ww + w0 + wq) * 9 + SOFF + t] = hsum_x2(acc[hr][wq][t]);
}

__global__ void __launch_bounds__(NT, 1)
cost_volume_kernel(const float* __restrict__ x1,
                   const float* __restrict__ x2,
                   float* __restrict__ out) {
    extern __shared__ float sm[];
    float* Bs = sm;                 // [136][132] swizzled; also A-staging slab at init
    float* Ps = sm + BS_FLOATS;     // [8][2][128][9] partials per c-group

    const int tid  = threadIdx.x;
    const int wp   = tid & 63;                // w-pair index
    const int w0   = wp << 1;                 // first w position
    const int cg   = tid >> 6;                // c-group 0..7, owns 16 ch at cg*16
    const int cbase = cg << 2;                // float4 col base
    const int bblk = blockIdx.x >> 6;
    const int h0   = (blockIdx.x & 63) << 1;
    const float invH = 1.0f / 128.0f;

    const float* x1b  = x1 + ((size_t)(bblk * Hh + h0)) * (Ww * Cc);
    const float* x2b  = x2 + ((size_t)bblk) * (Hh * Ww * Cc);
    float*       outb = out + ((size_t)(bblk * Hh + h0)) * (Ww * OC);

    // Edge bands: some (rw, i) channels have no valid x2 row -> pre-zero the band.
    if (h0 < 4 || h0 > 122) {
        for (int idx = tid; idx < 2 * Ww * OC; idx += NT) outb[idx] = 0.0f;
    }

    // ---- Load A into registers: a[hr][wq][8] u64 = 2 rows x 2 w x 16 c ----
    u64 a[2][2][8];
#pragma unroll
    for (int hc = 0; hc < 2; hc++) {
        // Stage x1 band c-half (64 ch) into Bs slab: coalesced.
        for (int idx = tid; idx < 2 * Ww * 16; idx += NT) {
            int row = idx >> 11;
            int rem = idx & 2047;
            int ww  = rem >> 4;
            int c4  = rem & 15;
            float4 v = *reinterpret_cast<const float4*>(
                x1b + (((row << 7) + ww) << 7) + (hc << 6) + (c4 << 2));
            *reinterpret_cast<float4*>(Bs + (row * Ww + ww) * APAD + (c4 << 2)) = v;
        }
        __syncthreads();
        if ((cg >> 2) == hc) {
            const int cl = (cg & 3) << 4;     // float offset within half
#pragma unroll
            for (int hr = 0; hr < 2; hr++)
#pragma unroll
                for (int wq = 0; wq < 2; wq++)
#pragma unroll
                    for (int k = 0; k < 4; k++) {
                        float4 v = *reinterpret_cast<const float4*>(
                            Bs + (hr * Ww + w0 + wq) * APAD + cl + (k << 2));
                        f4_to_u64(v, a[hr][wq][2 * k], a[hr][wq][2 * k + 1]);
                    }
        }
        __syncthreads();
    }

    // ---- Main loop over 10 x2 rows ----
    float* Pmy = Ps + cg * 2304;
    int pend = -1;
    for (int rr = 0; rr < 10; rr++) {
        const int r = h0 - 4 + rr;
        const bool rvalid = ((unsigned)r < (unsigned)Hh);

        __syncthreads();  // compute(rr-1) done reading Bs / writing Ps

        if (rvalid) stage_b(x2b, Bs, r, tid);            // GMEM latency overlapped by flush
        if (pend >= 0) flush_ps(Ps, outb, pend, tid, invH);

        __syncthreads();  // Bs staged; Ps consumed

        if (rvalid) {
            compute_pass<0>(a, Bs, Pmy, wp, w0, cbase);
            compute_pass<3>(a, Bs, Pmy, wp, w0, cbase);
            compute_pass<6>(a, Bs, Pmy, wp, w0, cbase);
            pend = rr;
        } else {
            pend = -1;
        }
    }
    __syncthreads();
    if (pend >= 0) flush_ps(Ps, outb, pend, tid, invH);
}

extern "C" void kernel_launch(void* const* d_in, const int* in_sizes, int n_in,
                              void* d_out, int out_size) {
    const float* x1 = (const float*)d_in[0];
    const float* x2 = (const float*)d_in[1];
    float* out = (float*)d_out;

    static bool attr_set = false;
    if (!attr_set) {
        cudaFuncSetAttribute(cost_volume_kernel,
                             cudaFuncAttributeMaxDynamicSharedMemorySize, SMEM_BYTES);
        attr_set = true;
    }

    dim3 grid(Bb * (Hh / 2));  // 512 blocks
    cost_volume_kernel<<<grid, NT, SMEM_BYTES>>>(x1, x2, out);
}

// round 12
// speedup vs baseline: 1.1335x; 1.0475x over previous
#include <cuda_runtime.h>
#include <cuda_bf16.h>

// Cost volume: out[b,h,w,(9i+jj)%81] = (1/H) * sum_c x1[b,h,w,c] * x2[b,h-i,w-jj,c]
// B=8, H=W=C=128, sr=4, D=9, OC=81. Zero padding outside.
//
// Block = (b, band of 2 output rows). 512 threads = 64 w-PAIRS x 8 c-groups (16 ch each).
// Each thread owns two adjacent w: a 3-slot pass needs 4 B-row loads for 12 dot-chains.
// B rows XOR-swizzled (c ^ ((row>>1)&7)) -> conflict-free at lane row-stride 2.
// A in registers (2h x 2w x 16c). B staging via cp.async (LDGSTS) into DOUBLE-BUFFERED Bs:
// copy of row rr+1 overlaps compute(rr); wait_group 1 at round head is then free.
// Partials in Ps[8]; flush(rr) in-round after 2nd barrier; write-once coalesced GMEM.
// Slot s reads Bs[w+s] = x2[r][w+s-4] => jj = 4 - s.

typedef unsigned long long u64;

#define Bb    8
#define Hh    128
#define Ww    128
#define Cc    128
#define OC    81
#define NT    512
#define BPAD  132        // Bs row stride: 528B (16B-aligned)
#define APAD  68         // A-staging stride: 272B (16B-aligned)
#define WB    136        // x2 row width incl. +/-4 halo

#define BS_FLOATS (WB * BPAD)            // 17952 per buffer (>= A-stage: 2*128*68 = 17408)
#define PS_FLOATS (8 * 2 * Ww * 9)       // 18432
#define SMEM_BYTES ((2 * BS_FLOATS + PS_FLOATS) * 4)   // 217344 B <= 232448

__device__ __forceinline__ u64 fmax2(u64 a, u64 b, u64 c) {
    u64 d;
    asm("fma.rn.f32x2 %0, %1, %2, %3;" : "=l"(d) : "l"(a), "l"(b), "l"(c));
    return d;
}
__device__ __forceinline__ float hsum_x2(u64 p) {
    float lo, hi;
    asm("mov.b64 {%0, %1}, %2;" : "=f"(lo), "=f"(hi) : "l"(p));
    return lo + hi;
}
__device__ __forceinline__ void f4_to_u64(const float4& v, u64& p0, u64& p1) {
    asm("mov.b64 %0, {%1, %2};" : "=l"(p0) : "f"(v.x), "f"(v.y));
    asm("mov.b64 %0, {%1, %2};" : "=l"(p1) : "f"(v.z), "f"(v.w));
}

// Async-stage x2 row r (full C, +/-4 halo zero-filled via zfill, XOR-swizzled columns).
__device__ __forceinline__ void stage_b_async(const float* __restrict__ x2b,
                                              unsigned bs_u32, int r, int tid) {
    for (int idx = tid; idx < WB * 32; idx += NT) {
        int wp = idx >> 5;
        int c4 = idx & 31;
        int w2 = wp - 4;
        int valid = ((unsigned)w2 < (unsigned)Ww);
        int w2c = valid ? w2 : 0;                       // clamped: address always in-bounds
        const float* src = x2b + (((r << 7) + w2c) << 7) + (c4 << 2);
        int srcsz = valid ? 16 : 0;                     // 0 -> 16B zero-fill
        int ce = c4 ^ ((wp >> 1) & 7);
        unsigned dst = bs_u32 + (unsigned)(wp * BPAD + (ce << 2)) * 4u;
        asm volatile("cp.async.cg.shared.global [%0], [%1], 16, %2;"
                     :: "r"(dst), "l"(src), "r"(srcsz));
    }
}

// Sum 8 c-group partials, scale, write final outputs for round rr.
__device__ __forceinline__ void flush_ps(const float* __restrict__ Ps,
                                         float* __restrict__ outb,
                                         int rr, int tid, float invH) {
    const int lo = (rr == 9) ? 1 : 0;
    const int hi = (rr == 0) ? 0 : 1;
    const int total = (hi - lo + 1) * Ww * 9;
    for (int idx = tid; idx < total; idx += NT) {
        int rowl = idx / (Ww * 9);
        int rem  = idx - rowl * (Ww * 9);
        int ww   = rem / 9;
        int s    = rem - ww * 9;
        int rw   = lo + rowl;
        int off  = (rw * Ww + ww) * 9 + s;
        float v = 0.0f;
#pragma unroll
        for (int g = 0; g < 8; g++) v += Ps[g * 2304 + off];
        int oc = 9 * (rw + 4 - rr) + (4 - s);   // i = h - r, jj = 4 - s
        if (oc < 0) oc += OC;
        outb[(size_t)(rw * Ww + ww) * OC + oc] = v * invH;
    }
}

// One slot pass: slots SOFF..SOFF+2 for both w-positions; 4 B-row loads per k-step.
template<int SOFF>
__device__ __forceinline__ void compute_pass(const u64 a[2][2][8],
                                             const float* __restrict__ Bs,
                                             float* __restrict__ Pmy,
                                             int wp, int w0, int cbase) {
    u64 acc[2][2][3];
#pragma unroll
    for (int hr = 0; hr < 2; hr++)
#pragma unroll
        for (int wq = 0; wq < 2; wq++)
#pragma unroll
            for (int t = 0; t < 3; t++) acc[hr][wq][t] = 0ull;

#pragma unroll
    for (int k = 0; k < 4; k++) {
        u64 b[4][2];
#pragma unroll
        for (int t = 0; t < 4; t++) {
            int R = w0 + SOFF + t;                        // B row (2wp + SOFF + t)
            int x = (wp + ((SOFF + t) >> 1)) & 7;         // (R>>1)&7
            float4 v = *reinterpret_cast<const float4*>(
                Bs + R * BPAD + (((cbase + k) ^ x) << 2));
            f4_to_u64(v, b[t][0], b[t][1]);
        }
#pragma unroll
        for (int hr = 0; hr < 2; hr++)
#pragma unroll
            for (int wq = 0; wq < 2; wq++)
#pragma unroll
                for (int t = 0; t < 3; t++) {
                    acc[hr][wq][t] = fmax2(a[hr][wq][2 * k],     b[wq + t][0], acc[hr][wq][t]);
                    acc[hr][wq][t] = fmax2(a[hr][wq][2 * k + 1], b[wq + t][1], acc[hr][wq][t]);
                }
    }
#pragma unroll
    for (int hr = 0; hr < 2; hr++)
#pragma unroll
        for (int wq = 0; wq < 2; wq++)
#pragma unroll
            for (int t = 0; t < 3; t++)
                Pmy[(hr * Ww + w0 + wq) * 9 + SOFF + t] = hsum_x2(acc[hr][wq][t]);
}

__global__ void __launch_bounds__(NT, 1)
cost_volume_kernel(const float* __restrict__ x1,
                   const float* __restrict__ x2,
                   float* __restrict__ out) {
    extern __shared__ float sm[];
    float* Bs0 = sm;                       // [136][132] swizzled, parity 0
    float* Bs1 = sm + BS_FLOATS;           // parity 1; also A-staging slab at init
    float* Ps  = sm + 2 * BS_FLOATS;       // [8][2][128][9] partials per c-group

    const int tid  = threadIdx.x;
    const int wp   = tid & 63;                // w-pair index
    const int w0   = wp << 1;                 // first w position
    const int cg   = tid >> 6;                // c-group 0..7, owns 16 ch at cg*16
    const int cbase = cg << 2;                // float4 col base
    const int bblk = blockIdx.x >> 6;
    const int h0   = (blockIdx.x & 63) << 1;
    const float invH = 1.0f / 128.0f;

    const float* x1b  = x1 + ((size_t)(bblk * Hh + h0)) * (Ww * Cc);
    const float* x2b  = x2 + ((size_t)bblk) * (Hh * Ww * Cc);
    float*       outb = out + ((size_t)(bblk * Hh + h0)) * (Ww * OC);

    const unsigned bs0_u32 = (unsigned)__cvta_generic_to_shared(Bs0);
    const unsigned bs1_u32 = (unsigned)__cvta_generic_to_shared(Bs1);

    // Edge bands: some (rw, i) channels have no valid x2 row -> pre-zero the band.
    if (h0 < 4 || h0 > 122) {
        for (int idx = tid; idx < 2 * Ww * OC; idx += NT) outb[idx] = 0.0f;
    }

    // Prologue: async-stage round 0's B row into Bs0 (group 0). Overlaps A staging below.
    {
        int r0 = h0 - 4;
        if ((unsigned)r0 < (unsigned)Hh) stage_b_async(x2b, bs0_u32, r0, tid);
        asm volatile("cp.async.commit_group;");
    }

    // ---- Load A into registers: a[hr][wq][8] u64 = 2 rows x 2 w x 16 c ----
    u64 a[2][2][8];
#pragma unroll
    for (int hc = 0; hc < 2; hc++) {
        for (int idx = tid; idx < 2 * Ww * 16; idx += NT) {
            int row = idx >> 11;
            int rem = idx & 2047;
            int ww  = rem >> 4;
            int c4  = rem & 15;
            float4 v = *reinterpret_cast<const float4*>(
                x1b + (((row << 7) + ww) << 7) + (hc << 6) + (c4 << 2));
            *reinterpret_cast<float4*>(Bs1 + (row * Ww + ww) * APAD + (c4 << 2)) = v;
        }
        __syncthreads();
        if ((cg >> 2) == hc) {
            const int cl = (cg & 3) << 4;     // float offset within half
#pragma unroll
            for (int hr = 0; hr < 2; hr++)
#pragma unroll
                for (int wq = 0; wq < 2; wq++)
#pragma unroll
                    for (int k = 0; k < 4; k++) {
                        float4 v = *reinterpret_cast<const float4*>(
                            Bs1 + (hr * Ww + w0 + wq) * APAD + cl + (k << 2));
                        f4_to_u64(v, a[hr][wq][2 * k], a[hr][wq][2 * k + 1]);
                    }
        }
        __syncthreads();
    }

    // ---- Main loop over 10 x2 rows: one cp.async group per round ----
    float* Pmy = Ps + cg * 2304;
    for (int rr = 0; rr < 10; rr++) {
        const int r = h0 - 4 + rr;
        const bool rvalid = ((unsigned)r < (unsigned)Hh);

        // 1. Issue next round's staging into the other buffer (fire-and-forget).
        if (rr < 9) {
            int rn = h0 - 4 + rr + 1;
            if ((unsigned)rn < (unsigned)Hh)
                stage_b_async(x2b, (rr & 1) ? bs0_u32 : bs1_u32, rn, tid);
        }
        asm volatile("cp.async.commit_group;");   // always commit (uniform group count)

        // 2. Wait for THIS round's staging (all groups but the newest one).
        asm volatile("cp.async.wait_group 1;");
        __syncthreads();   // everyone's stage(rr) visible; Ps free (flushed last round)

        // 3. Compute round rr.
        if (rvalid) {
            const float* Bcur = (rr & 1) ? Bs1 : Bs0;
            compute_pass<0>(a, Bcur, Pmy, wp, w0, cbase);
            compute_pass<3>(a, Bcur, Pmy, wp, w0, cbase);
            compute_pass<6>(a, Bcur, Pmy, wp, w0, cbase);
        }
        __syncthreads();   // Ps complete

        // 4. Flush round rr to GMEM (cp.async of round rr+1 still in flight underneath).
        if (rvalid) flush_ps(Ps, outb, rr, tid, invH);
    }
}

extern "C" void kernel_launch(void* const* d_in, const int* in_sizes, int n_in,
                              void* d_out, int out_size) {
    const float* x1 = (const float*)d_in[0];
    const float* x2 = (const float*)d_in[1];
    float* out = (float*)d_out;

    static bool attr_set = false;
    if (!attr_set) {
        cudaFuncSetAttribute(cost_volume_kernel,
                             cudaFuncAttributeMaxDynamicSharedMemorySize, SMEM_BYTES);
        attr_set = true;
    }

    dim3 grid(Bb * (Hh / 2));  // 512 blocks
    cost_volume_kernel<<<grid, NT, SMEM_BYTES>>>(x1, x2, out);
}

// round 13
// speedup vs baseline: 1.1924x; 1.0520x over previous
#include <cuda_runtime.h>
#include <cuda_bf16.h>

// Cost volume: out[b,h,w,(9i+jj)%81] = (1/H) * sum_c x1[b,h,w,c] * x2[b,h-i,w-jj,c]
// B=8, H=W=C=128, sr=4, D=9, OC=81. Zero padding outside.
//
// Block = (b, band of 2 rows, HALF of the 10 x2 rounds). 1024 blocks (tail-packed).
// Halves own disjoint output channels (oc determined by rr) -> independent, write-once.
// 512 threads = 64 w-pairs x 8 c-groups (16ch). A in registers. B staged via cp.async
// into double-buffered Bs (BPAD=128, XOR swizzle c4^((row>>1)&7), conflict-free).
// Halo rows pre-zeroed once; staging is branch-free. Invalid rounds write zeros directly.
// Slot s reads Bs[w+s] = x2[r][w+s-4] => jj = 4 - s.

typedef unsigned long long u64;

#define Bb    8
#define Hh    128
#define Ww    128
#define Cc    128
#define OC    81
#define NT    512
#define APAD  68         // A-staging stride: 272B (16B-aligned), conflict-free

#define BS_FLOATS (136 * 128)          // 17408 per buffer (== A-stage 2*128*68 exactly)
#define PS_FLOATS (8 * 2 * Ww * 9)     // 18432
#define SMEM_BYTES ((2 * BS_FLOATS + PS_FLOATS) * 4)   // 212992 B

__device__ __forceinline__ u64 fmax2(u64 a, u64 b, u64 c) {
    u64 d;
    asm("fma.rn.f32x2 %0, %1, %2, %3;" : "=l"(d) : "l"(a), "l"(b), "l"(c));
    return d;
}
__device__ __forceinline__ float hsum_x2(u64 p) {
    float lo, hi;
    asm("mov.b64 {%0, %1}, %2;" : "=f"(lo), "=f"(hi) : "l"(p));
    return lo + hi;
}
__device__ __forceinline__ void f4_to_u64(const float4& v, u64& p0, u64& p1) {
    asm("mov.b64 %0, {%1, %2};" : "=l"(p0) : "f"(v.x), "f"(v.y));
    asm("mov.b64 %0, {%1, %2};" : "=l"(p1) : "f"(v.z), "f"(v.w));
}

// Async-stage x2 row r: interior rows only (halo pre-zeroed), branch-free, 4096 LDGSTS.
__device__ __forceinline__ void stage_b_async(const float* __restrict__ x2b,
                                              unsigned bs_u32, int r, int tid) {
    for (int idx = tid; idx < 4096; idx += NT) {
        int wp4 = idx >> 5;                  // 0..127 = w position
        int c4  = idx & 31;
        int wp  = wp4 + 4;                   // Bs row 4..131
        const float* src = x2b + (((r << 7) + wp4) << 7) + (c4 << 2);
        int ce = c4 ^ ((wp >> 1) & 7);
        unsigned dst = bs_u32 + (unsigned)((wp << 7) + (ce << 2)) * 4u;
        asm volatile("cp.async.cg.shared.global [%0], [%1], 16;"
                     :: "r"(dst), "l"(src));
    }
}

// Sum 8 c-group partials, scale, write final outputs for global round rr.
__device__ __forceinline__ void flush_ps(const float* __restrict__ Ps,
                                         float* __restrict__ outb,
                                         int rr, int tid, float invH) {
    const int lo = (rr == 9) ? 1 : 0;
    const int hi = (rr == 0) ? 0 : 1;
    const int total = (hi - lo + 1) * Ww * 9;
    for (int idx = tid; idx < total; idx += NT) {
        int rowl = idx / (Ww * 9);
        int rem  = idx - rowl * (Ww * 9);
        int ww   = rem / 9;
        int s    = rem - ww * 9;
        int rw   = lo + rowl;
        int off  = (rw * Ww + ww) * 9 + s;
        float v = 0.0f;
#pragma unroll
        for (int g = 0; g < 8; g++) v += Ps[g * 2304 + off];
        int oc = 9 * (rw + 4 - rr) + (4 - s);   // i = h - r, jj = 4 - s
        if (oc < 0) oc += OC;
        outb[(size_t)(rw * Ww + ww) * OC + oc] = v * invH;
    }
}

// Invalid x2 row: this half-block still owns round rr's channels -> write zeros.
__device__ __forceinline__ void flush_zero(float* __restrict__ outb,
                                           int rr, int tid) {
    const int lo = (rr == 9) ? 1 : 0;
    const int hi = (rr == 0) ? 0 : 1;
    const int total = (hi - lo + 1) * Ww * 9;
    for (int idx = tid; idx < total; idx += NT) {
        int rowl = idx / (Ww * 9);
        int rem  = idx - rowl * (Ww * 9);
        int ww   = rem / 9;
        int s    = rem - ww * 9;
        int rw   = lo + rowl;
        int oc = 9 * (rw + 4 - rr) + (4 - s);
        if (oc < 0) oc += OC;
        outb[(size_t)(rw * Ww + ww) * OC + oc] = 0.0f;
    }
}

// One slot pass: slots SOFF..SOFF+2 for both w-positions; 4 B-row loads per k-step.
template<int SOFF>
__device__ __forceinline__ void compute_pass(const u64 a[2][2][8],
                                             const float* __restrict__ Bs,
                                             float* __restrict__ Pmy,
                                             int wp, int w0, int cbase) {
    u64 acc[2][2][3];
#pragma unroll
    for (int hr = 0; hr < 2; hr++)
#pragma unroll
        for (int wq = 0; wq < 2; wq++)
#pragma unroll
            for (int t = 0; t < 3; t++) acc[hr][wq][t] = 0ull;

#pragma unroll
    for (int k = 0; k < 4; k++) {
        u64 b[4][2];
#pragma unroll
        for (int t = 0; t < 4; t++) {
            int R = w0 + SOFF + t;                        // B row
            int x = (wp + ((SOFF + t) >> 1)) & 7;         // (R>>1)&7
            float4 v = *reinterpret_cast<const float4*>(
                Bs + (R << 7) + (((cbase + k) ^ x) << 2));
            f4_to_u64(v, b[t][0], b[t][1]);
        }
#pragma unroll
        for (int hr = 0; hr < 2; hr++)
#pragma unroll
            for (int wq = 0; wq < 2; wq++)
#pragma unroll
                for (int t = 0; t < 3; t++) {
                    acc[hr][wq][t] = fmax2(a[hr][wq][2 * k],     b[wq + t][0], acc[hr][wq][t]);
                    acc[hr][wq][t] = fmax2(a[hr][wq][2 * k + 1], b[wq + t][1], acc[hr][wq][t]);
                }
    }
#pragma unroll
    for (int hr = 0; hr < 2; hr++)
#pragma unroll
        for (int wq = 0; wq < 2; wq++)
#pragma unroll
            for (int t = 0; t < 3; t++)
                Pmy[(hr * Ww + w0 + wq) * 9 + SOFF + t] = hsum_x2(acc[hr][wq][t]);
}

__global__ void __launch_bounds__(NT, 1)
cost_volume_kernel(const float* __restrict__ x1,
                   const float* __restrict__ x2,
                   float* __restrict__ out) {
    extern __shared__ float sm[];
    float* Bs0 = sm;                       // [136][128] swizzled, parity 0
    float* Bs1 = sm + BS_FLOATS;           // parity 1; also A-staging slab at init
    float* Ps  = sm + 2 * BS_FLOATS;       // [8][2][128][9] partials per c-group

    const int tid  = threadIdx.x;
    const int wp   = tid & 63;                // w-pair index
    const int w0   = wp << 1;
    const int cg   = tid >> 6;                // c-group 0..7 (16 ch at cg*16)
    const int cbase = cg << 2;                // float4 col base
    const int bx   = blockIdx.x;
    const int half = bx & 1;                  // rounds 0-4 or 5-9
    const int h0   = ((bx >> 1) & 63) << 1;
    const int bblk = bx >> 7;
    const int rr0  = half * 5;
    const float invH = 1.0f / 128.0f;

    const float* x1b  = x1 + ((size_t)(bblk * Hh + h0)) * (Ww * Cc);
    const float* x2b  = x2 + ((size_t)bblk) * (Hh * Ww * Cc);
    float*       outb = out + ((size_t)(bblk * Hh + h0)) * (Ww * OC);

    const unsigned bs0_u32 = (unsigned)__cvta_generic_to_shared(Bs0);
    const unsigned bs1_u32 = (unsigned)__cvta_generic_to_shared(Bs1);

    // Prologue: async-stage first round's B row into Bs0 (interior only).
    {
        int r0 = h0 - 4 + rr0;
        if ((unsigned)r0 < (unsigned)Hh) stage_b_async(x2b, bs0_u32, r0, tid);
        asm volatile("cp.async.commit_group;");
    }

    // ---- Load A into registers: a[hr][wq][8] u64 = 2 rows x 2 w x 16 c ----
    u64 a[2][2][8];
#pragma unroll
    for (int hc = 0; hc < 2; hc++) {
        for (int idx = tid; idx < 2 * Ww * 16; idx += NT) {
            int row = idx >> 11;
            int rem = idx & 2047;
            int ww  = rem >> 4;
            int c4  = rem & 15;
            float4 v = *reinterpret_cast<const float4*>(
                x1b + (((row << 7) + ww) << 7) + (hc << 6) + (c4 << 2));
            *reinterpret_cast<float4*>(Bs1 + (row * Ww + ww) * APAD + (c4 << 2)) = v;
        }
        __syncthreads();
        if ((cg >> 2) == hc) {
            const int cl = (cg & 3) << 4;
#pragma unroll
            for (int hr = 0; hr < 2; hr++)
#pragma unroll
                for (int wq = 0; wq < 2; wq++)
#pragma unroll
                    for (int k = 0; k < 4; k++) {
                        float4 v = *reinterpret_cast<const float4*>(
                            Bs1 + (hr * Ww + w0 + wq) * APAD + cl + (k << 2));
                        f4_to_u64(v, a[hr][wq][2 * k], a[hr][wq][2 * k + 1]);
                    }
        }
        __syncthreads();
    }

    // Zero halo rows (0-3, 132-135) of BOTH buffers once. 512 float4 stores.
    // Bs1's A-slab overlapped these -> must be after A-load. Staging never touches them.
    {
        int b   = tid >> 8;            // buffer 0/1
        int rem = tid & 255;
        int hrw = rem >> 5;            // 0..7
        int row = hrw + ((hrw >= 4) ? 128 : 0);
        int c4  = rem & 31;
        float* bp = b ? Bs1 : Bs0;
        *reinterpret_cast<float4*>(bp + (row << 7) + (c4 << 2)) =
            make_float4(0.f, 0.f, 0.f, 0.f);
    }

    // ---- Main loop over this half's 5 rounds ----
    float* Pmy = Ps + cg * 2304;
    for (int j = 0; j < 5; j++) {
        const int rrg = rr0 + j;
        const int r = h0 - 4 + rrg;
        const bool rvalid = ((unsigned)r < (unsigned)Hh);

        // 1. Issue next round's staging into the other buffer.
        if (j < 4) {
            int rn = r + 1;
            if ((unsigned)rn < (unsigned)Hh)
                stage_b_async(x2b, (j & 1) ? bs0_u32 : bs1_u32, rn, tid);
        }
        asm volatile("cp.async.commit_group;");   // uniform group count

        // Invalid round: our channels still need zeros (overlaps cp.async copies).
        if (!rvalid) flush_zero(outb, rrg, tid);

        // 2. Wait for THIS round's staging.
        asm volatile("cp.async.wait_group 1;");
        __syncthreads();

        // 3. Compute round rrg.
        if (rvalid) {
            const float* Bcur = (j & 1) ? Bs1 : Bs0;
            compute_pass<0>(a, Bcur, Pmy, wp, w0, cbase);
            compute_pass<3>(a, Bcur, Pmy, wp, w0, cbase);
            compute_pass<6>(a, Bcur, Pmy, wp, w0, cbase);
        }
        __syncthreads();

        // 4. Flush round rrg (cp.async of round rrg+1 still in flight underneath).
        if (rvalid) flush_ps(Ps, outb, rrg, tid, invH);
    }
}

extern "C" void kernel_launch(void* const* d_in, const int* in_sizes, int n_in,
                              void* d_out, int out_size) {
    const float* x1 = (const float*)d_in[0];
    const float* x2 = (const float*)d_in[1];
    float* out = (float*)d_out;

    static bool attr_set = false;
    if (!attr_set) {
        cudaFuncSetAttribute(cost_volume_kernel,
                             cudaFuncAttributeMaxDynamicSharedMemorySize, SMEM_BYTES);
        attr_set = true;
    }

    dim3 grid(Bb * 64 * 2);  // 1024 half-blocks: better tail packing
    cost_volume_kernel<<<grid, NT, SMEM_BYTES>>>(x1, x2, out);
}

// round 14
// speedup vs baseline: 1.2236x; 1.0262x over previous
#include <cuda_runtime.h>
#include <cuda_bf16.h>

// Cost volume: out[b,h,w,(9i+jj)%81] = (1/H) * sum_c x1[b,h,w,c] * x2[b,h-i,w-jj,c]
// B=8, H=W=C=128, sr=4, D=9, OC=81. Zero padding outside.
//
// Block = (b, band of 2 rows, HALF of the 10 x2 rounds). 1024 blocks (tail-packed).
// Halves own disjoint output channels -> independent, write-once.
// 512 threads = 64 w-pairs x 8 c-groups (16ch). A in registers (loaded via cp.async slab).
// B staged via cp.async into double-buffered Bs (BPAD=128, XOR swizzle c4^((row>>1)&7)).
// Halo rows pre-zeroed once. Partials in Ps[8]; flush uses incremental indexing.
// Slot s reads Bs[w+s] = x2[r][w+s-4] => jj = 4 - s.

typedef unsigned long long u64;

#define Bb    8
#define Hh    128
#define Ww    128
#define Cc    128
#define OC    81
#define NT    512
#define APAD  68         // A-staging stride: 272B (16B-aligned)

#define BS_FLOATS (136 * 128)          // 17408 per buffer (== A-stage 2*128*68 exactly)
#define PS_FLOATS (8 * 2 * Ww * 9)     // 18432
#define SMEM_BYTES ((2 * BS_FLOATS + PS_FLOATS) * 4)   // 212992 B

__device__ __forceinline__ u64 fmax2(u64 a, u64 b, u64 c) {
    u64 d;
    asm("fma.rn.f32x2 %0, %1, %2, %3;" : "=l"(d) : "l"(a), "l"(b), "l"(c));
    return d;
}
__device__ __forceinline__ float hsum_x2(u64 p) {
    float lo, hi;
    asm("mov.b64 {%0, %1}, %2;" : "=f"(lo), "=f"(hi) : "l"(p));
    return lo + hi;
}
__device__ __forceinline__ void f4_to_u64(const float4& v, u64& p0, u64& p1) {
    asm("mov.b64 %0, {%1, %2};" : "=l"(p0) : "f"(v.x), "f"(v.y));
    asm("mov.b64 %0, {%1, %2};" : "=l"(p1) : "f"(v.z), "f"(v.w));
}

// Async-stage x2 row r: interior rows only (halo pre-zeroed), branch-free, 4096 LDGSTS.
__device__ __forceinline__ void stage_b_async(const float* __restrict__ x2b,
                                              unsigned bs_u32, int r, int tid) {
    for (int idx = tid; idx < 4096; idx += NT) {
        int wp4 = idx >> 5;                  // 0..127 = w position
        int c4  = idx & 31;
        int wp  = wp4 + 4;                   // Bs row 4..131
        const float* src = x2b + (((r << 7) + wp4) << 7) + (c4 << 2);
        int ce = c4 ^ ((wp >> 1) & 7);
        unsigned dst = bs_u32 + (unsigned)((wp << 7) + (ce << 2)) * 4u;
        asm volatile("cp.async.cg.shared.global [%0], [%1], 16;"
                     :: "r"(dst), "l"(src));
    }
}

// Sum 8 c-group partials, scale, write final outputs for global round rr.
// Incremental (pos, s) indexing: NT = 56*9 + 8.
__device__ __forceinline__ void flush_ps(const float* __restrict__ Ps,
                                         float* __restrict__ outb,
                                         int rr, int tid, float invH) {
    const int lo = (rr == 9) ? 1 : 0;
    const int hi = (rr == 0) ? 0 : 1;
    const int total = (hi - lo + 1) * Ww * 9;
    int pos = tid / 9;                 // output index within (rows x 128 w)
    int s   = tid - pos * 9;
    const int obase = lo * Ww;         // first active (rw*Ww) offset
    for (int idx = tid; idx < total; idx += NT) {
        int off = (obase + pos) * 9 + s;
        float v = 0.0f;
#pragma unroll
        for (int g = 0; g < 8; g++) v += Ps[g * 2304 + off];
        int rw = lo + (pos >> 7);
        int oc = 9 * (rw + 4 - rr) + (4 - s);   // i = h - r, jj = 4 - s
        if (oc < 0) oc += OC;
        int ww = pos & 127;
        outb[(size_t)(rw * Ww + ww) * OC + oc] = v * invH;
        pos += 56; s += 8;
        if (s >= 9) { s -= 9; pos++; }
    }
}

// Invalid x2 row: this half-block still owns round rr's channels -> write zeros.
__device__ __forceinline__ void flush_zero(float* __restrict__ outb,
                                           int rr, int tid) {
    const int lo = (rr == 9) ? 1 : 0;
    const int hi = (rr == 0) ? 0 : 1;
    const int total = (hi - lo + 1) * Ww * 9;
    int pos = tid / 9;
    int s   = tid - pos * 9;
    for (int idx = tid; idx < total; idx += NT) {
        int rw = lo + (pos >> 7);
        int oc = 9 * (rw + 4 - rr) + (4 - s);
        if (oc < 0) oc += OC;
        int ww = pos & 127;
        outb[(size_t)(rw * Ww + ww) * OC + oc] = 0.0f;
        pos += 56; s += 8;
        if (s >= 9) { s -= 9; pos++; }
    }
}

// One slot pass: slots SOFF..SOFF+2 for both w-positions; 4 B-row loads per k-step.
template<int SOFF>
__device__ __forceinline__ void compute_pass(const u64 a[2][2][8],
                                             const float* __restrict__ Bs,
                                             float* __restrict__ Pmy,
                                             int wp, int w0, int cbase) {
    u64 acc[2][2][3];
#pragma unroll
    for (int hr = 0; hr < 2; hr++)
#pragma unroll
        for (int wq = 0; wq < 2; wq++)
#pragma unroll
            for (int t = 0; t < 3; t++) acc[hr][wq][t] = 0ull;

#pragma unroll
    for (int k = 0; k < 4; k++) {
        u64 b[4][2];
#pragma unroll
        for (int t = 0; t < 4; t++) {
            int R = w0 + SOFF + t;                        // B row
            int x = (wp + ((SOFF + t) >> 1)) & 7;         // (R>>1)&7
            float4 v = *reinterpret_cast<const float4*>(
                Bs + (R << 7) + (((cbase + k) ^ x) << 2));
            f4_to_u64(v, b[t][0], b[t][1]);
        }
#pragma unroll
        for (int hr = 0; hr < 2; hr++)
#pragma unroll
            for (int wq = 0; wq < 2; wq++)
#pragma unroll
                for (int t = 0; t < 3; t++) {
                    acc[hr][wq][t] = fmax2(a[hr][wq][2 * k],     b[wq + t][0], acc[hr][wq][t]);
                    acc[hr][wq][t] = fmax2(a[hr][wq][2 * k + 1], b[wq + t][1], acc[hr][wq][t]);
                }
    }
#pragma unroll
    for (int hr = 0; hr < 2; hr++)
#pragma unroll
        for (int wq = 0; wq < 2; wq++)
#pragma unroll
            for (int t = 0; t < 3; t++)
                Pmy[(hr * Ww + w0 + wq) * 9 + SOFF + t] = hsum_x2(acc[hr][wq][t]);
}

__global__ void __launch_bounds__(NT, 1)
cost_volume_kernel(const float* __restrict__ x1,
                   const float* __restrict__ x2,
                   float* __restrict__ out) {
    extern __shared__ float sm[];
    float* Bs0 = sm;                       // [136][128] swizzled, parity 0
    float* Bs1 = sm + BS_FLOATS;           // parity 1; also A-staging slab at init
    float* Ps  = sm + 2 * BS_FLOATS;       // [8][2][128][9] partials per c-group

    const int tid  = threadIdx.x;
    const int wp   = tid & 63;                // w-pair index
    const int w0   = wp << 1;
    const int cg   = tid >> 6;                // c-group 0..7 (16 ch at cg*16)
    const int cbase = cg << 2;                // float4 col base
    const int bx   = blockIdx.x;
    const int half = bx & 1;                  // rounds 0-4 or 5-9
    const int h0   = ((bx >> 1) & 63) << 1;
    const int bblk = bx >> 7;
    const int rr0  = half * 5;
    const float invH = 1.0f / 128.0f;

    const float* x1b  = x1 + ((size_t)(bblk * Hh + h0)) * (Ww * Cc);
    const float* x2b  = x2 + ((size_t)bblk) * (Hh * Ww * Cc);
    float*       outb = out + ((size_t)(bblk * Hh + h0)) * (Ww * OC);

    const unsigned bs0_u32  = (unsigned)__cvta_generic_to_shared(Bs0);
    const unsigned bs1_u32  = (unsigned)__cvta_generic_to_shared(Bs1);
    const unsigned slab_u32 = bs1_u32;

    // Prologue: async-stage first round's B row into Bs0 (interior only). Group A.
    {
        int r0 = h0 - 4 + rr0;
        if ((unsigned)r0 < (unsigned)Hh) stage_b_async(x2b, bs0_u32, r0, tid);
        asm volatile("cp.async.commit_group;");
    }

    // ---- Load A into registers via cp.async slab (2 c-halves through Bs1) ----
    u64 a[2][2][8];
#pragma unroll
    for (int hc = 0; hc < 2; hc++) {
        for (int idx = tid; idx < 2 * Ww * 16; idx += NT) {
            int row = idx >> 11;
            int rem = idx & 2047;
            int ww  = rem >> 4;
            int c4  = rem & 15;
            const float* src = x1b + (((row << 7) + ww) << 7) + (hc << 6) + (c4 << 2);
            unsigned dst = slab_u32 + (unsigned)((row * Ww + ww) * APAD + (c4 << 2)) * 4u;
            asm volatile("cp.async.cg.shared.global [%0], [%1], 16;"
                         :: "r"(dst), "l"(src));
        }
        asm volatile("cp.async.commit_group;");
        asm volatile("cp.async.wait_group 0;");   // also drains prologue B group (harmless)
        __syncthreads();
        if ((cg >> 2) == hc) {
            const int cl = (cg & 3) << 4;
#pragma unroll
            for (int hr = 0; hr < 2; hr++)
#pragma unroll
                for (int wq = 0; wq < 2; wq++)
#pragma unroll
                    for (int k = 0; k < 4; k++) {
                        float4 v = *reinterpret_cast<const float4*>(
                            Bs1 + (hr * Ww + w0 + wq) * APAD + cl + (k << 2));
                        f4_to_u64(v, a[hr][wq][2 * k], a[hr][wq][2 * k + 1]);
                    }
        }
        __syncthreads();
    }

    // Zero halo rows (0-3, 132-135) of BOTH buffers once. 512 float4 stores.
    // Bs1's A-slab overlapped these -> must be after A-load. Staging never touches them.
    {
        int b   = tid >> 8;            // buffer 0/1
        int rem = tid & 255;
        int hrw = rem >> 5;            // 0..7
        int row = hrw + ((hrw >= 4) ? 128 : 0);
        int c4  = rem & 31;
        float* bp = b ? Bs1 : Bs0;
        *reinterpret_cast<float4*>(bp + (row << 7) + (c4 << 2)) =
            make_float4(0.f, 0.f, 0.f, 0.f);
    }

    // ---- Main loop over this half's 5 rounds ----
    float* Pmy = Ps + cg * 2304;
    for (int j = 0; j < 5; j++) {
        const int rrg = rr0 + j;
        const int r = h0 - 4 + rrg;
        const bool rvalid = ((unsigned)r < (unsigned)Hh);

        // 1. Issue next round's staging into the other buffer.
        if (j < 4) {
            int rn = r + 1;
            if ((unsigned)rn < (unsigned)Hh)
                stage_b_async(x2b, (j & 1) ? bs0_u32 : bs1_u32, rn, tid);
        }
        asm volatile("cp.async.commit_group;");   // uniform group count

        // Invalid round: our channels still need zeros (overlaps cp.async copies).
        if (!rvalid) flush_zero(outb, rrg, tid);

        // 2. Wait for THIS round's staging.
        asm volatile("cp.async.wait_group 1;");
        __syncthreads();

        // 3. Compute round rrg.
        if (rvalid) {
            const float* Bcur = (j & 1) ? Bs1 : Bs0;
            compute_pass<0>(a, Bcur, Pmy, wp, w0, cbase);
            compute_pass<3>(a, Bcur, Pmy, wp, w0, cbase);
            compute_pass<6>(a, Bcur, Pmy, wp, w0, cbase);
        }
        __syncthreads();

        // 4. Flush round rrg (cp.async of round rrg+1 still in flight underneath).
        if (rvalid) flush_ps(Ps, outb, rrg, tid, invH);
    }
}

extern "C" void kernel_launch(void* const* d_in, const int* in_sizes, int n_in,
                              void* d_out, int out_size) {
    const float* x1 = (const float*)d_in[0];
    const float* x2 = (const float*)d_in[1];
    float* out = (float*)d_out;

    static bool attr_set = false;
    if (!attr_set) {
        cudaFuncSetAttribute(cost_volume_kernel,
                             cudaFuncAttributeMaxDynamicSharedMemorySize, SMEM_BYTES);
        attr_set = true;
    }

    dim3 grid(Bb * 64 * 2);  // 1024 half-blocks
    cost_volume_kernel<<<grid, NT, SMEM_BYTES>>>(x1, x2, out);
}